// round 10
// baseline (speedup 1.0000x reference)
#include <cuda_runtime.h>
#include <math.h>
#include <stdint.h>
#include <stddef.h>

#define N_NODES 131072
#define E_EDGES 2097152
#define B_PAIRS 4096
#define R_REL   5
#define L_LAYERS 4
#define T_STEPS 4096

// ---------------- device scratch (static globals; no runtime allocation) ----
static __device__ float g_relfeat[(size_t)N_NODES * R_REL * 32];  // 80 MB
static __device__ float g_agg[(size_t)N_NODES * 32];              // 16 MB
static __device__ float g_states[(size_t)N_NODES * 128];          // 64 MB
static __device__ int   g_cnt[(size_t)N_NODES * R_REL];           // 2.5 MB
static __device__ float g_weff[L_LAYERS * 32 * 192];              // 96 KB
static __device__ float g_z [(size_t)B_PAIRS * 256];              // 4 MB
static __device__ float g_xg[(size_t)T_STEPS * 1024];             // 16 MB
static __device__ unsigned long long g_h1p[(size_t)T_STEPS * 256];   // packed (h, tag)
static __device__ unsigned long long g_h2p[(size_t)T_STEPS * 256];   // packed (h, tag)
static __device__ unsigned long long g_xg2p[(size_t)T_STEPS * 1024]; // packed (xg2, tag) 32MB

// ---------------- packed publish/poll: scalar b64 + acquire/release ---------
// EMPIRICALLY LOAD-BEARING: weak b64 (.cv/.cg) and v2.u32 variants both
// produced rel_err ~0.3 (stale payload visible with fresh tag). Keep strong.
__device__ __forceinline__ float poll_word(const unsigned long long* p, unsigned tag) {
    unsigned long long w;
    do {
        asm volatile("ld.global.acquire.gpu.b64 %0, [%1];"
                     : "=l"(w) : "l"(p) : "memory");
    } while ((unsigned)(w >> 32) != tag);
    return __uint_as_float((unsigned)(w & 0xffffffffull));
}
__device__ __forceinline__ void publish_word(unsigned long long* p, float h, unsigned tag) {
    unsigned long long w = ((unsigned long long)tag << 32)
                         | (unsigned long long)__float_as_uint(h);
    asm volatile("st.global.release.gpu.b64 [%0], %1;"
                 :: "l"(p), "l"(w) : "memory");
}

// ---------------- cluster / mbarrier helpers --------------------------------
__device__ __forceinline__ uint32_t smem_u32(const void* p) {
    uint32_t a;
    asm("{ .reg .u64 t; cvta.to.shared.u64 t, %1; cvt.u32.u64 %0, t; }"
        : "=r"(a) : "l"(p));
    return a;
}
__device__ __forceinline__ void mbar_init(uint32_t addr, uint32_t cnt) {
    asm volatile("mbarrier.init.shared.b64 [%0], %1;" :: "r"(addr), "r"(cnt) : "memory");
}
__device__ __forceinline__ void mbar_arrive_expect(uint32_t addr, uint32_t tx) {
    asm volatile("mbarrier.arrive.expect_tx.shared.b64 _, [%0], %1;"
                 :: "r"(addr), "r"(tx) : "memory");
}
__device__ __forceinline__ void mbar_wait_cluster(uint32_t addr, int phase) {
    asm volatile(
        "{\n\t"
        ".reg .pred P;\n\t"
        "WAITL_%=:\n\t"
        "mbarrier.try_wait.parity.acquire.cluster.shared::cta.b64 P, [%0], %1, 0x989680;\n\t"
        "@P bra.uni WDONE_%=;\n\t"
        "bra.uni WAITL_%=;\n\t"
        "WDONE_%=:\n\t"
        "}"
        :: "r"(addr), "r"(phase) : "memory");
}
__device__ __forceinline__ uint32_t mapa_u32(uint32_t addr, uint32_t rank) {
    uint32_t r;
    asm("mapa.shared::cluster.u32 %0, %1, %2;" : "=r"(r) : "r"(addr), "r"(rank));
    return r;
}
// 128-byte DSMEM bulk copy; completes tx-bytes on the TARGET CTA's mbarrier.
__device__ __forceinline__ void dsmem_bulk128(uint32_t dst, uint32_t src, uint32_t mbar) {
    asm volatile(
        "cp.async.bulk.shared::cluster.shared::cta.mbarrier::complete_tx::bytes "
        "[%0], [%1], 128, [%2];"
        :: "r"(dst), "r"(src), "r"(mbar) : "memory");
}
__device__ __forceinline__ void fence_proxy_async_cta() {
    asm volatile("fence.proxy.async.shared::cta;" ::: "memory");
}
__device__ __forceinline__ void cluster_sync_() {
    asm volatile("barrier.cluster.arrive.aligned;" ::: "memory");
    asm volatile("barrier.cluster.wait.aligned;" ::: "memory");
}

// ---------------- init: zero counts ------------------------------------------
__global__ void k_init() {
    int i = blockIdx.x * blockDim.x + threadIdx.x;
    if (i < N_NODES * R_REL) g_cnt[i] = 0;
}

// ---------------- zero ALL packed tag buffers (graph-replay safe) ------------
__global__ void k_zerotags() {
    size_t i = (size_t)blockIdx.x * blockDim.x + threadIdx.x;
    if (i < (size_t)T_STEPS * 1024) g_xg2p[i] = 0ull;
    if (i < (size_t)T_STEPS * 256) { g_h1p[i] = 0ull; g_h2p[i] = 0ull; }
}

// ---------------- per-(dst,rel) edge counts ----------------------------------
__global__ void k_count(const int* __restrict__ ei, const int* __restrict__ et) {
    int e = blockIdx.x * blockDim.x + threadIdx.x;
    if (e >= E_EDGES) return;
    int dst = ei[E_EDGES + e];
    int r   = et[e];
    atomicAdd(&g_cnt[(size_t)dst * R_REL + r], 1);
}

// ---------------- effective relation weights ---------------------------------
__global__ void k_weff(const float* __restrict__ basis,
                       const float* __restrict__ comp,
                       const float* __restrict__ root) {
    int idx = blockIdx.x * blockDim.x + threadIdx.x;
    if (idx >= L_LAYERS * 32 * 192) return;
    int l = idx / (32 * 192);
    int rem = idx % (32 * 192);
    int i = rem / 192;
    int o = rem % 192;
    int r = o / 32, j = o % 32;
    float v;
    if (r < R_REL) {
        v = 0.f;
        #pragma unroll
        for (int b = 0; b < 4; b++)
            v += comp[(l * R_REL + r) * 4 + b] * basis[(((size_t)l * 4 + b) * 32 + i) * 32 + j];
    } else {
        v = root[((size_t)l * 32 + i) * 32 + j];
    }
    g_weff[idx] = v;
}

// ---------------- node transform ---------------------------------------------
__global__ void k_transform(const float* __restrict__ x,
                            const float* __restrict__ cbias, int l) {
    __shared__ __align__(16) float hs[32][32];
    int n0 = blockIdx.x * 32;
    int tid = threadIdx.x;  // 0..191

    for (int i = tid; i < 1024; i += 192) {
        int m = i >> 5, c = i & 31;
        float v;
        if (l == 0) v = x[(size_t)(n0 + m) * 32 + c];
        else        v = g_states[(size_t)(n0 + m) * 128 + (l - 1) * 32 + c];
        hs[m][c] = v;
    }
    float wreg[32];
    const float* W = g_weff + l * 32 * 192;
    #pragma unroll
    for (int i = 0; i < 32; i++) wreg[i] = W[i * 192 + tid];
    __syncthreads();

    int r = tid / 32, o = tid % 32;
    float bias = (r == 5) ? cbias[o] : 0.f;

    for (int m = 0; m < 32; m++) {
        const float4* hp = (const float4*)hs[m];
        float acc = 0.f;
        #pragma unroll
        for (int i4 = 0; i4 < 8; i4++) {
            float4 h4 = hp[i4];
            acc += h4.x * wreg[i4 * 4 + 0];
            acc += h4.y * wreg[i4 * 4 + 1];
            acc += h4.z * wreg[i4 * 4 + 2];
            acc += h4.w * wreg[i4 * 4 + 3];
        }
        if (r < R_REL)
            g_relfeat[((size_t)(n0 + m) * R_REL + r) * 32 + o] = acc;
        else
            g_agg[(size_t)(n0 + m) * 32 + o] = acc + bias;
    }
}

// ---------------- edge aggregation: 8 lanes/edge, vector reductions ----------
__global__ void k_edge(const int* __restrict__ ei, const int* __restrict__ et) {
    int gid = blockIdx.x * blockDim.x + threadIdx.x;
    int e = gid >> 3;
    int q = gid & 7;
    if (e >= E_EDGES) return;
    int src = ei[e];
    int dst = ei[E_EDGES + e];
    int r   = et[e];
    int cnt = g_cnt[(size_t)dst * R_REL + r];
    float norm = 1.0f / (float)(cnt < 1 ? 1 : cnt);
    float4 v = *(const float4*)&g_relfeat[((size_t)src * R_REL + r) * 32 + q * 4];
    float* p = &g_agg[(size_t)dst * 32 + q * 4];
    asm volatile("red.global.add.v4.f32 [%0], {%1,%2,%3,%4};"
                 :: "l"(p), "f"(v.x * norm), "f"(v.y * norm),
                    "f"(v.z * norm), "f"(v.w * norm)
                 : "memory");
}

// ---------------- tanh into concat states ------------------------------------
__global__ void k_tanh(int l) {
    int i = blockIdx.x * blockDim.x + threadIdx.x;
    if (i >= N_NODES * 32) return;
    int n = i >> 5, o = i & 31;
    g_states[(size_t)n * 128 + l * 32 + o] = tanhf(g_agg[i]);
}

// ---------------- gather z = [states[user], states[item]] --------------------
__global__ void k_gather(const int* __restrict__ ui, const int* __restrict__ vi) {
    int i = blockIdx.x * blockDim.x + threadIdx.x;
    if (i >= B_PAIRS * 256) return;
    int b = i >> 8, o = i & 255;
    int node = (o < 128) ? ui[b] : vi[b];
    g_z[i] = g_states[(size_t)node * 128 + (o & 127)];
}

// ---------------- x-gates GEMM for layer 0 ------------------------------------
__global__ void __launch_bounds__(256)
k_xg(const float* __restrict__ wih, const float* __restrict__ bih,
     const float* __restrict__ bhh) {
    __shared__ __align__(16) float As[32][65];
    __shared__ __align__(16) float Bs[32][65];
    int tid = threadIdx.x;
    int m0 = blockIdx.y * 64, n0 = blockIdx.x * 64;
    int tm = tid >> 4, tn = tid & 15;
    float acc[4][4];
    #pragma unroll
    for (int u = 0; u < 4; u++)
        #pragma unroll
        for (int v = 0; v < 4; v++) acc[u][v] = 0.f;

    for (int k0 = 0; k0 < 256; k0 += 32) {
        for (int i = tid; i < 512; i += 256) {
            int mm = i >> 3, kq = i & 7;
            float4 v = *(const float4*)&g_z[(size_t)(m0 + mm) * 256 + k0 + kq * 4];
            As[kq * 4 + 0][mm] = v.x; As[kq * 4 + 1][mm] = v.y;
            As[kq * 4 + 2][mm] = v.z; As[kq * 4 + 3][mm] = v.w;
        }
        for (int i = tid; i < 512; i += 256) {
            int nn = i >> 3, kq = i & 7;
            float4 v = *(const float4*)&wih[(size_t)(n0 + nn) * 256 + k0 + kq * 4];
            Bs[kq * 4 + 0][nn] = v.x; Bs[kq * 4 + 1][nn] = v.y;
            Bs[kq * 4 + 2][nn] = v.z; Bs[kq * 4 + 3][nn] = v.w;
        }
        __syncthreads();
        #pragma unroll
        for (int kk = 0; kk < 32; kk++) {
            float a[4], b[4];
            #pragma unroll
            for (int u = 0; u < 4; u++) { a[u] = As[kk][tm * 4 + u]; b[u] = Bs[kk][tn * 4 + u]; }
            #pragma unroll
            for (int u = 0; u < 4; u++)
                #pragma unroll
                for (int v = 0; v < 4; v++) acc[u][v] += a[u] * b[v];
        }
        __syncthreads();
    }
    #pragma unroll
    for (int u = 0; u < 4; u++)
        #pragma unroll
        for (int v = 0; v < 4; v++) {
            int rr = n0 + tn * 4 + v;
            g_xg[(size_t)(m0 + tm * 4 + u) * 1024 + rr] = acc[u][v] + bih[rr] + bhh[rr];
        }
}

// ---------------- fused cluster scan ------------------------------------------
// 32 CTAs x 512 thr, clusterDim=8 (PORTABLE max; no non-portable attribute).
//  blocks 0-7   (cluster 0): layer-0 recurrence, W_hh0 regs, DSMEM h1 all-gather
//  blocks 8-15  (cluster 1): layer-1 recurrence, W_hh1 regs, DSMEM h2 all-gather
//  blocks 16-31 (clusters 2,3): xg2 GEMV stage: polls h1 (L2), computes
//       xg2=W_ih1*h1+b, publishes tagged words (pipeline lag, latency-tolerant)
// Recurrence layers: CTA crank owns 32 h; warp w -> h j = crank*32+2w+{0,1};
// half-warp per h: lane = hs*16 + p*4 + s (gate p, 64-col slice s, 64 w-regs).
// Per step: ONE mbarrier wait (expect-tx 1024B) instead of L2 poll; publish =
// 8x 128B cp.async.bulk DSMEM copies. Buffer/expect reuse safety: entering
// step t+2's wait proves peers consumed our step-t copies (delivered => read).
__global__ void __launch_bounds__(512, 1)
k_scan_fused(const float* __restrict__ wih_g, const float* __restrict__ whh_g,
             const float* __restrict__ bih, const float* __restrict__ bhh) {
    __shared__ __align__(16) float hA[2][256];     // DSMEM-gathered own-layer h
    __shared__ __align__(16) float hstage[2][32];  // local 32 h staging (128 B)
    __shared__ __align__(16) float h1s[2][256];    // role C: h1(t)
    __shared__ __align__(8) unsigned long long barA[2];
    int blk = blockIdx.x;
    int tid = threadIdx.x;

    if (blk < 16) {
        // ---------------- roles A (layer 0) and B (layer 1) ----------------
        int layer = blk >> 3;
        uint32_t crank;
        asm("mov.u32 %0, %%cluster_ctarank;" : "=r"(crank));
        int w = tid >> 5, lane = tid & 31;
        int hs = lane >> 4, r = lane & 15;
        int p = r >> 2, s = r & 3;
        int j = (int)crank * 32 + w * 2 + hs;   // h index 0..255
        int row = p * 256 + j;                  // gate row 0..1023

        // W_hh[layer] row, cols s*64..s*64+63, column-staggered (m = (qq+s*4)&15)
        float wreg[64];
        {
            const float* W = whh_g + (size_t)layer * 262144 + (size_t)row * 256 + s * 64;
            #pragma unroll
            for (int qq = 0; qq < 16; qq++) {
                int m = (qq + s * 4) & 15;
                float4 v = *(const float4*)&W[m * 4];
                wreg[4*qq] = v.x; wreg[4*qq+1] = v.y; wreg[4*qq+2] = v.z; wreg[4*qq+3] = v.w;
            }
        }

        uint32_t bar0 = smem_u32(&barA[0]);
        uint32_t bar1 = smem_u32(&barA[1]);
        if (tid == 0) { mbar_init(bar0, 1); mbar_init(bar1, 1); }
        __syncthreads();
        if (tid == 0) { mbar_arrive_expect(bar0, 1024); mbar_arrive_expect(bar1, 1024); }
        cluster_sync_();

        // bulk-copy routes: warp 0 lane k (<8) -> peer CTA k
        uint32_t dst0 = 0, dst1 = 0, mb0 = 0, mb1 = 0;
        uint32_t src0 = smem_u32(&hstage[0][0]);
        uint32_t src1 = smem_u32(&hstage[1][0]);
        if (w == 0 && lane < 8) {
            dst0 = mapa_u32(smem_u32(&hA[0][crank * 32]), (uint32_t)lane);
            dst1 = mapa_u32(smem_u32(&hA[1][crank * 32]), (uint32_t)lane);
            mb0  = mapa_u32(bar0, (uint32_t)lane);
            mb1  = mapa_u32(bar1, (uint32_t)lane);
        }

        int ph0 = 0, ph1 = 0;
        float cst = 0.f;

        #pragma unroll 1
        for (int t = 0; t < T_STEPS; t++) {
            int buf = t & 1;
            int pb = (t - 1) & 1;

            float xg = 0.f;
            if (s == 0) {
                if (layer == 0) xg = __ldg(&g_xg[(size_t)t * 1024 + row]);
                else            xg = poll_word(&g_xg2p[(size_t)t * 1024 + row],
                                               (unsigned)(t + 1));
            }

            if (t > 0) {
                if (pb == 0) {
                    mbar_wait_cluster(bar0, ph0); ph0 ^= 1;
                    if (tid == 0) mbar_arrive_expect(bar0, 1024);
                } else {
                    mbar_wait_cluster(bar1, ph1); ph1 ^= 1;
                    if (tid == 0) mbar_arrive_expect(bar1, 1024);
                }
            }

            float a0 = 0.f, a1 = 0.f, a2 = 0.f, a3 = 0.f;
            if (t > 0) {
                const float4* hp = (const float4*)&hA[pb][0];
                #pragma unroll
                for (int qq = 0; qq < 16; qq++) {
                    int m = (qq + s * 4) & 15;
                    float4 h4 = hp[s * 16 + m];
                    a0 += wreg[4*qq]   * h4.x;
                    a1 += wreg[4*qq+1] * h4.y;
                    a2 += wreg[4*qq+2] * h4.z;
                    a3 += wreg[4*qq+3] * h4.w;
                }
            }
            float acc = (a0 + a1) + (a2 + a3);
            acc += __shfl_xor_sync(0xffffffffu, acc, 1);
            acc += __shfl_xor_sync(0xffffffffu, acc, 2);

            float gact = 0.f;
            if (s == 0) {
                float gv = acc + xg;
                gact = (p == 2) ? tanhf(gv) : __fdividef(1.f, 1.f + __expf(-gv));
            }
            int base = hs * 16;
            float gi = __shfl_sync(0xffffffffu, gact, base + 0);
            float gf = __shfl_sync(0xffffffffu, gact, base + 4);
            float gg = __shfl_sync(0xffffffffu, gact, base + 8);
            float go = __shfl_sync(0xffffffffu, gact, base + 12);

            if (r == 0) {
                cst = gf * cst + gi * gg;
                float h = go * tanhf(cst);
                hstage[buf][w * 2 + hs] = h;
                // L2 publish: layer0 -> xg2 stage; layer1 -> k_head
                publish_word((layer == 0) ? &g_h1p[(size_t)t * 256 + j]
                                          : &g_h2p[(size_t)t * 256 + j],
                             h, (unsigned)(t + 1));
            }
            __syncthreads();
            if (w == 0) {
                fence_proxy_async_cta();
                if (lane < 8)
                    dsmem_bulk128(buf ? dst1 : dst0, buf ? src1 : src0,
                                  buf ? mb1 : mb0);
            }
        }
        cluster_sync_();
    } else {
        // ---------------- role C: xg2 GEMV stage ----------------
        int c = blk - 16;                       // 0..15
        int rowc = c * 64 + (tid >> 3);         // gate row 0..1023
        int sub = tid & 7;                      // 32-col slice
        float wreg[32];
        {
            const float* W = wih_g + (size_t)262144 + (size_t)rowc * 256 + sub * 32;
            #pragma unroll
            for (int qq = 0; qq < 8; qq++) {
                int m = (qq + sub) & 7;
                float4 v = *(const float4*)&W[m * 4];
                wreg[4*qq] = v.x; wreg[4*qq+1] = v.y; wreg[4*qq+2] = v.z; wreg[4*qq+3] = v.w;
            }
        }
        float bias = (sub == 0) ? (bih[1024 + rowc] + bhh[1024 + rowc]) : 0.f;

        #pragma unroll 1
        for (int t = 0; t < T_STEPS; t++) {
            int buf = t & 1;
            if (tid < 256)
                h1s[buf][tid] = poll_word(&g_h1p[(size_t)t * 256 + tid],
                                          (unsigned)(t + 1));
            __syncthreads();

            float a0 = 0.f, a1 = 0.f, a2 = 0.f, a3 = 0.f;
            const float4* hp = (const float4*)&h1s[buf][sub * 32];
            #pragma unroll
            for (int qq = 0; qq < 8; qq++) {
                int m = (qq + sub) & 7;
                float4 h4 = hp[m];
                a0 += wreg[4*qq]   * h4.x;
                a1 += wreg[4*qq+1] * h4.y;
                a2 += wreg[4*qq+2] * h4.z;
                a3 += wreg[4*qq+3] * h4.w;
            }
            float acc = (a0 + a1) + (a2 + a3);
            acc += __shfl_xor_sync(0xffffffffu, acc, 1);
            acc += __shfl_xor_sync(0xffffffffu, acc, 2);
            acc += __shfl_xor_sync(0xffffffffu, acc, 4);
            if (sub == 0)
                publish_word(&g_xg2p[(size_t)t * 1024 + rowc], acc + bias,
                             (unsigned)(t + 1));
        }
    }
}

// ---------------- fallback L2-tag scan (round-9 proven, 7.3ms) ----------------
__global__ void __launch_bounds__(256, 1)
k_scan(const float* __restrict__ wih_g, const float* __restrict__ whh_g,
       const float* __restrict__ bih, const float* __restrict__ bhh) {
    int blk = blockIdx.x;
    int layer = blk >> 5;
    int k = blk & 31;
    int tid = threadIdx.x;
    int w = tid >> 5, lane = tid & 31;
    int p = lane >> 3, s = lane & 7;
    int j = k * 8 + w;
    int row = p * 256 + j;

    float wih[32], whh[32];
    {
        const float* WhhP = whh_g + (size_t)layer * 262144 + (size_t)row * 256 + s * 32;
        #pragma unroll
        for (int c = 0; c < 32; c++) whh[c] = WhhP[c];
    }
    if (layer == 1) {
        const float* WihP = wih_g + (size_t)262144 + (size_t)row * 256 + s * 32;
        #pragma unroll
        for (int c = 0; c < 32; c++) wih[c] = WihP[c];
    } else {
        #pragma unroll
        for (int c = 0; c < 32; c++) wih[c] = 0.f;
    }
    float bias = 0.f;
    if (layer == 1 && s == 0) bias = bih[1024 + row] + bhh[1024 + row];

    unsigned long long* outp = (layer == 0) ? g_h1p : g_h2p;
    __shared__ __align__(16) float hA[2][288];
    __shared__ __align__(16) float hX[2][288];
    float cst = 0.f;

    #pragma unroll 1
    for (int t = 0; t < T_STEPS; t++) {
        int buf = t & 1;
        float xg = 0.f;
        if (layer == 0 && s == 0)
            xg = __ldg(&g_xg[(size_t)t * 1024 + row]);

        int pos = (tid >> 5) * 36 + (tid & 31);
        if (layer == 0) {
            if (t > 0)
                hA[buf][pos] = poll_word(&g_h1p[(size_t)(t - 1) * 256 + tid], (unsigned)t);
        } else {
            hX[buf][pos] = poll_word(&g_h1p[(size_t)t * 256 + tid], (unsigned)(t + 1));
            if (t > 0)
                hA[buf][pos] = poll_word(&g_h2p[(size_t)(t - 1) * 256 + tid], (unsigned)t);
        }
        __syncthreads();

        float a0 = 0.f, a1 = 0.f, a2 = 0.f, a3 = 0.f;
        if (layer == 0) {
            if (t > 0) {
                const float4* hp = (const float4*)&hA[buf][s * 36];
                #pragma unroll
                for (int q = 0; q < 8; q++) {
                    float4 h4 = hp[q];
                    a0 += whh[4*q]   * h4.x;
                    a1 += whh[4*q+1] * h4.y;
                    a2 += whh[4*q+2] * h4.z;
                    a3 += whh[4*q+3] * h4.w;
                }
            }
        } else {
            const float4* xp = (const float4*)&hX[buf][s * 36];
            #pragma unroll
            for (int q = 0; q < 8; q++) {
                float4 h4 = xp[q];
                a0 += wih[4*q]   * h4.x;
                a1 += wih[4*q+1] * h4.y;
                a2 += wih[4*q+2] * h4.z;
                a3 += wih[4*q+3] * h4.w;
            }
            if (t > 0) {
                const float4* hp = (const float4*)&hA[buf][s * 36];
                #pragma unroll
                for (int q = 0; q < 8; q++) {
                    float4 h4 = hp[q];
                    a0 += whh[4*q]   * h4.x;
                    a1 += whh[4*q+1] * h4.y;
                    a2 += whh[4*q+2] * h4.z;
                    a3 += whh[4*q+3] * h4.w;
                }
            }
        }
        float acc = (a0 + a1) + (a2 + a3);
        acc += __shfl_xor_sync(0xffffffffu, acc, 4);
        acc += __shfl_xor_sync(0xffffffffu, acc, 2);
        acc += __shfl_xor_sync(0xffffffffu, acc, 1);

        float gact = 0.f;
        if (s == 0) {
            float gv = acc + bias + xg;
            gact = (p == 2) ? tanhf(gv) : __fdividef(1.f, 1.f + __expf(-gv));
        }
        float gi = __shfl_sync(0xffffffffu, gact, 0);
        float gf = __shfl_sync(0xffffffffu, gact, 8);
        float gg = __shfl_sync(0xffffffffu, gact, 16);
        float go = __shfl_sync(0xffffffffu, gact, 24);

        if (lane == 0) {
            cst = gf * cst + gi * gg;
            float h = go * tanhf(cst);
            publish_word(&outp[(size_t)t * 256 + j], h, (unsigned)(t + 1));
        }
    }
}

// ---------------- final MLP head ----------------------------------------------
__global__ void k_head(const float* __restrict__ l1w, const float* __restrict__ l1b,
                       const float* __restrict__ l2w, const float* __restrict__ l2b,
                       float* __restrict__ out) {
    int b = blockIdx.x;
    int tid = threadIdx.x;  // 256 threads
    int w = tid >> 5, lane = tid & 31;
    __shared__ __align__(16) float hs[256];
    __shared__ float rs[128];
    __shared__ float part[8];

    hs[tid] = __uint_as_float((unsigned)(g_h2p[(size_t)b * 256 + tid] & 0xffffffffull));
    __syncthreads();

    for (int q = 0; q < 16; q++) {
        int jrow = w * 16 + q;
        const float4* wp = (const float4*)(l1w + (size_t)jrow * 256 + lane * 8);
        float4 wa = wp[0], wb = wp[1];
        const float4* hp = (const float4*)(hs + lane * 8);
        float4 haa = hp[0], hbb = hp[1];
        float acc = wa.x * haa.x + wa.y * haa.y + wa.z * haa.z + wa.w * haa.w
                  + wb.x * hbb.x + wb.y * hbb.y + wb.z * hbb.z + wb.w * hbb.w;
        #pragma unroll
        for (int sft = 16; sft > 0; sft >>= 1)
            acc += __shfl_xor_sync(0xffffffffu, acc, sft);
        if (lane == 0) rs[jrow] = fmaxf(acc + l1b[jrow], 0.f);
    }
    __syncthreads();

    float v = (tid < 128) ? rs[tid] * l2w[tid] : 0.f;
    #pragma unroll
    for (int sft = 16; sft > 0; sft >>= 1)
        v += __shfl_xor_sync(0xffffffffu, v, sft);
    if (lane == 0) part[w] = v;
    __syncthreads();
    if (tid == 0) {
        float sum = 0.f;
        #pragma unroll
        for (int i = 0; i < 8; i++) sum += part[i];
        out[b] = sum + l2b[0];
    }
}

// ---------------- launch --------------------------------------------------------
extern "C" void kernel_launch(void* const* d_in, const int* in_sizes, int n_in,
                              void* d_out, int out_size) {
    const float* x     = (const float*)d_in[0];
    const int*   ei    = (const int*)  d_in[1];
    const int*   et    = (const int*)  d_in[2];
    const int*   ui    = (const int*)  d_in[3];
    const int*   vi    = (const int*)  d_in[4];
    const float* basis = (const float*)d_in[5];
    const float* comp  = (const float*)d_in[6];
    const float* root  = (const float*)d_in[7];
    const float* cbias = (const float*)d_in[8];
    const float* w_ih  = (const float*)d_in[9];
    const float* w_hh  = (const float*)d_in[10];
    const float* b_ih  = (const float*)d_in[11];
    const float* b_hh  = (const float*)d_in[12];
    const float* l1w   = (const float*)d_in[13];
    const float* l1b   = (const float*)d_in[14];
    const float* l2w   = (const float*)d_in[15];
    const float* l2b   = (const float*)d_in[16];
    float* out = (float*)d_out;

    k_init<<<(N_NODES * R_REL + 255) / 256, 256>>>();
    k_zerotags<<<(T_STEPS * 1024 + 255) / 256, 256>>>();
    k_count<<<(E_EDGES + 255) / 256, 256>>>(ei, et);
    k_weff<<<(L_LAYERS * 32 * 192 + 255) / 256, 256>>>(basis, comp, root);

    for (int l = 0; l < L_LAYERS; l++) {
        k_transform<<<N_NODES / 32, 192>>>(x, cbias + l * 32, l);
        k_edge<<<((size_t)E_EDGES * 8) / 256, 256>>>(ei, et);
        k_tanh<<<(N_NODES * 32) / 256, 256>>>(l);
    }

    k_gather<<<(B_PAIRS * 256) / 256, 256>>>(ui, vi);
    k_xg<<<dim3(16, 64), 256>>>(w_ih, b_ih, b_hh);

    // fused DSMEM scan: 8-CTA (portable) clusters; fallback to proven L2 scan
    bool launched = false;
    {
        cudaLaunchConfig_t cfg = {};
        cfg.gridDim = dim3(32, 1, 1);
        cfg.blockDim = dim3(512, 1, 1);
        cfg.dynamicSmemBytes = 0;
        cudaLaunchAttribute attrs[1];
        attrs[0].id = cudaLaunchAttributeClusterDimension;
        attrs[0].val.clusterDim.x = 8;
        attrs[0].val.clusterDim.y = 1;
        attrs[0].val.clusterDim.z = 1;
        cfg.attrs = attrs;
        cfg.numAttrs = 1;
        int nclus = 0;
        cudaError_t qrc = cudaOccupancyMaxActiveClusters(&nclus, k_scan_fused, &cfg);
        if (qrc == cudaSuccess && nclus >= 4) {
            if (cudaLaunchKernelEx(&cfg, k_scan_fused, w_ih, w_hh, b_ih, b_hh)
                == cudaSuccess)
                launched = true;
        }
    }
    if (!launched)
        k_scan<<<64, 256>>>(w_ih, w_hh, b_ih, b_hh);

    k_head<<<B_PAIRS, 256>>>(l1w, l1b, l2w, l2b, out);
}

// round 11
// speedup vs baseline: 1.3614x; 1.3614x over previous
#include <cuda_runtime.h>
#include <math.h>
#include <stdint.h>
#include <stddef.h>

#define N_NODES 131072
#define E_EDGES 2097152
#define B_PAIRS 4096
#define R_REL   5
#define L_LAYERS 4
#define T_STEPS 4096

// ---------------- device scratch (static globals; no runtime allocation) ----
static __device__ float g_relfeat[(size_t)N_NODES * R_REL * 32];  // 80 MB
static __device__ float g_agg[(size_t)N_NODES * 32];              // 16 MB
static __device__ float g_states[(size_t)N_NODES * 128];          // 64 MB
static __device__ int   g_cnt[(size_t)N_NODES * R_REL];           // 2.5 MB
static __device__ float g_weff[L_LAYERS * 32 * 192];              // 96 KB
static __device__ float g_z [(size_t)B_PAIRS * 256];              // 4 MB
static __device__ float g_xg[(size_t)T_STEPS * 1024];             // 16 MB
static __device__ unsigned long long g_h1p[(size_t)T_STEPS * 256];   // packed (h, tag)
static __device__ unsigned long long g_h2p[(size_t)T_STEPS * 256];   // packed (h, tag)
static __device__ unsigned long long g_xg2p[(size_t)T_STEPS * 1024]; // packed (xg2, tag)

// ---------------- packed publish/poll: scalar b64 + acquire/release ---------
// EMPIRICALLY LOAD-BEARING: weak b64 (.cv/.cg) and v2.u32 variants both
// produced rel_err ~0.3 (stale payload visible with fresh tag). Keep strong.
__device__ __forceinline__ float poll_word(const unsigned long long* p, unsigned tag) {
    unsigned long long w;
    do {
        asm volatile("ld.global.acquire.gpu.b64 %0, [%1];"
                     : "=l"(w) : "l"(p) : "memory");
    } while ((unsigned)(w >> 32) != tag);
    return __uint_as_float((unsigned)(w & 0xffffffffull));
}
__device__ __forceinline__ unsigned long long load_word(const unsigned long long* p) {
    unsigned long long w;
    asm volatile("ld.global.acquire.gpu.b64 %0, [%1];"
                 : "=l"(w) : "l"(p) : "memory");
    return w;
}
__device__ __forceinline__ void publish_word(unsigned long long* p, float h, unsigned tag) {
    unsigned long long w = ((unsigned long long)tag << 32)
                         | (unsigned long long)__float_as_uint(h);
    asm volatile("st.global.release.gpu.b64 [%0], %1;"
                 :: "l"(p), "l"(w) : "memory");
}

// ---------------- init: zero counts ------------------------------------------
__global__ void k_init() {
    int i = blockIdx.x * blockDim.x + threadIdx.x;
    if (i < N_NODES * R_REL) g_cnt[i] = 0;
}

// ---------------- zero ALL packed tag buffers (graph-replay safe) ------------
__global__ void k_zerotags() {
    size_t i = (size_t)blockIdx.x * blockDim.x + threadIdx.x;
    if (i < (size_t)T_STEPS * 1024) g_xg2p[i] = 0ull;
    if (i < (size_t)T_STEPS * 256) { g_h1p[i] = 0ull; g_h2p[i] = 0ull; }
}

// ---------------- per-(dst,rel) edge counts ----------------------------------
__global__ void k_count(const int* __restrict__ ei, const int* __restrict__ et) {
    int e = blockIdx.x * blockDim.x + threadIdx.x;
    if (e >= E_EDGES) return;
    int dst = ei[E_EDGES + e];
    int r   = et[e];
    atomicAdd(&g_cnt[(size_t)dst * R_REL + r], 1);
}

// ---------------- effective relation weights ---------------------------------
__global__ void k_weff(const float* __restrict__ basis,
                       const float* __restrict__ comp,
                       const float* __restrict__ root) {
    int idx = blockIdx.x * blockDim.x + threadIdx.x;
    if (idx >= L_LAYERS * 32 * 192) return;
    int l = idx / (32 * 192);
    int rem = idx % (32 * 192);
    int i = rem / 192;
    int o = rem % 192;
    int r = o / 32, j = o % 32;
    float v;
    if (r < R_REL) {
        v = 0.f;
        #pragma unroll
        for (int b = 0; b < 4; b++)
            v += comp[(l * R_REL + r) * 4 + b] * basis[(((size_t)l * 4 + b) * 32 + i) * 32 + j];
    } else {
        v = root[((size_t)l * 32 + i) * 32 + j];
    }
    g_weff[idx] = v;
}

// ---------------- node transform ---------------------------------------------
__global__ void k_transform(const float* __restrict__ x,
                            const float* __restrict__ cbias, int l) {
    __shared__ __align__(16) float hs[32][32];
    int n0 = blockIdx.x * 32;
    int tid = threadIdx.x;  // 0..191

    for (int i = tid; i < 1024; i += 192) {
        int m = i >> 5, c = i & 31;
        float v;
        if (l == 0) v = x[(size_t)(n0 + m) * 32 + c];
        else        v = g_states[(size_t)(n0 + m) * 128 + (l - 1) * 32 + c];
        hs[m][c] = v;
    }
    float wreg[32];
    const float* W = g_weff + l * 32 * 192;
    #pragma unroll
    for (int i = 0; i < 32; i++) wreg[i] = W[i * 192 + tid];
    __syncthreads();

    int r = tid / 32, o = tid % 32;
    float bias = (r == 5) ? cbias[o] : 0.f;

    for (int m = 0; m < 32; m++) {
        const float4* hp = (const float4*)hs[m];
        float acc = 0.f;
        #pragma unroll
        for (int i4 = 0; i4 < 8; i4++) {
            float4 h4 = hp[i4];
            acc += h4.x * wreg[i4 * 4 + 0];
            acc += h4.y * wreg[i4 * 4 + 1];
            acc += h4.z * wreg[i4 * 4 + 2];
            acc += h4.w * wreg[i4 * 4 + 3];
        }
        if (r < R_REL)
            g_relfeat[((size_t)(n0 + m) * R_REL + r) * 32 + o] = acc;
        else
            g_agg[(size_t)(n0 + m) * 32 + o] = acc + bias;
    }
}

// ---------------- edge aggregation: 8 lanes/edge, vector reductions ----------
__global__ void k_edge(const int* __restrict__ ei, const int* __restrict__ et) {
    int gid = blockIdx.x * blockDim.x + threadIdx.x;
    int e = gid >> 3;
    int q = gid & 7;
    if (e >= E_EDGES) return;
    int src = ei[e];
    int dst = ei[E_EDGES + e];
    int r   = et[e];
    int cnt = g_cnt[(size_t)dst * R_REL + r];
    float norm = 1.0f / (float)(cnt < 1 ? 1 : cnt);
    float4 v = *(const float4*)&g_relfeat[((size_t)src * R_REL + r) * 32 + q * 4];
    float* p = &g_agg[(size_t)dst * 32 + q * 4];
    asm volatile("red.global.add.v4.f32 [%0], {%1,%2,%3,%4};"
                 :: "l"(p), "f"(v.x * norm), "f"(v.y * norm),
                    "f"(v.z * norm), "f"(v.w * norm)
                 : "memory");
}

// ---------------- tanh into concat states ------------------------------------
__global__ void k_tanh(int l) {
    int i = blockIdx.x * blockDim.x + threadIdx.x;
    if (i >= N_NODES * 32) return;
    int n = i >> 5, o = i & 31;
    g_states[(size_t)n * 128 + l * 32 + o] = tanhf(g_agg[i]);
}

// ---------------- gather z = [states[user], states[item]] --------------------
__global__ void k_gather(const int* __restrict__ ui, const int* __restrict__ vi) {
    int i = blockIdx.x * blockDim.x + threadIdx.x;
    if (i >= B_PAIRS * 256) return;
    int b = i >> 8, o = i & 255;
    int node = (o < 128) ? ui[b] : vi[b];
    g_z[i] = g_states[(size_t)node * 128 + (o & 127)];
}

// ---------------- x-gates GEMM for layer 0 ------------------------------------
__global__ void __launch_bounds__(256)
k_xg(const float* __restrict__ wih, const float* __restrict__ bih,
     const float* __restrict__ bhh) {
    __shared__ __align__(16) float As[32][65];
    __shared__ __align__(16) float Bs[32][65];
    int tid = threadIdx.x;
    int m0 = blockIdx.y * 64, n0 = blockIdx.x * 64;
    int tm = tid >> 4, tn = tid & 15;
    float acc[4][4];
    #pragma unroll
    for (int u = 0; u < 4; u++)
        #pragma unroll
        for (int v = 0; v < 4; v++) acc[u][v] = 0.f;

    for (int k0 = 0; k0 < 256; k0 += 32) {
        for (int i = tid; i < 512; i += 256) {
            int mm = i >> 3, kq = i & 7;
            float4 v = *(const float4*)&g_z[(size_t)(m0 + mm) * 256 + k0 + kq * 4];
            As[kq * 4 + 0][mm] = v.x; As[kq * 4 + 1][mm] = v.y;
            As[kq * 4 + 2][mm] = v.z; As[kq * 4 + 3][mm] = v.w;
        }
        for (int i = tid; i < 512; i += 256) {
            int nn = i >> 3, kq = i & 7;
            float4 v = *(const float4*)&wih[(size_t)(n0 + nn) * 256 + k0 + kq * 4];
            Bs[kq * 4 + 0][nn] = v.x; Bs[kq * 4 + 1][nn] = v.y;
            Bs[kq * 4 + 2][nn] = v.z; Bs[kq * 4 + 3][nn] = v.w;
        }
        __syncthreads();
        #pragma unroll
        for (int kk = 0; kk < 32; kk++) {
            float a[4], b[4];
            #pragma unroll
            for (int u = 0; u < 4; u++) { a[u] = As[kk][tm * 4 + u]; b[u] = Bs[kk][tn * 4 + u]; }
            #pragma unroll
            for (int u = 0; u < 4; u++)
                #pragma unroll
                for (int v = 0; v < 4; v++) acc[u][v] += a[u] * b[v];
        }
        __syncthreads();
    }
    #pragma unroll
    for (int u = 0; u < 4; u++)
        #pragma unroll
        for (int v = 0; v < 4; v++) {
            int rr = n0 + tn * 4 + v;
            g_xg[(size_t)(m0 + tm * 4 + u) * 1024 + rr] = acc[u][v] + bih[rr] + bhh[rr];
        }
}

// ---------------- persistent 2-layer LSTM scan + xg2 stage (L2 tag words) ----
// 96 CTAs x 256 threads.
//   blocks 0..31  : layer-0 recurrence (W_hh0 in regs, x-gates from g_xg)
//   blocks 32..63 : layer-1 recurrence (W_hh1 in regs, x-gates from g_xg2p)
//   blocks 64..95 : xg2 stage: polls h1(t), computes W_ih1*h1(t)+bias,
//                   publishes tagged xg2 words (pipeline lag, latency-tolerant)
// Recurrence CTA k owns h-indices [8k,8k+8); warp w -> j=8k+w. Lane = p*8+s.
// Layer 1 critical path: speculative 1-word xg2 acquire issued BEFORE the
// h2(t-1) spin, verified after (hits first try since xg2 stage runs ahead).
__global__ void __launch_bounds__(256, 1)
k_scan(const float* __restrict__ wih_g, const float* __restrict__ whh_g,
       const float* __restrict__ bih, const float* __restrict__ bhh) {
    int blk = blockIdx.x;
    int tid = threadIdx.x;

    if (blk >= 64) {
        // ---------------- xg2 GEMV stage ----------------
        int c = blk - 64;                 // 0..31
        int rowc = c * 32 + (tid >> 3);   // gate row 0..1023
        int sub = tid & 7;                // 32-col slice
        float wr[32];
        {
            const float* W = wih_g + (size_t)262144 + (size_t)rowc * 256 + sub * 32;
            #pragma unroll
            for (int q = 0; q < 32; q++) wr[q] = W[q];
        }
        float bias = (sub == 0) ? (bih[1024 + rowc] + bhh[1024 + rowc]) : 0.f;
        __shared__ __align__(16) float h1s[2][288];

        #pragma unroll 1
        for (int t = 0; t < T_STEPS; t++) {
            int buf = t & 1;
            int pos = (tid >> 5) * 36 + (tid & 31);
            h1s[buf][pos] = poll_word(&g_h1p[(size_t)t * 256 + tid], (unsigned)(t + 1));
            __syncthreads();

            float a0 = 0.f, a1 = 0.f, a2 = 0.f, a3 = 0.f;
            const float4* hp = (const float4*)&h1s[buf][sub * 36];
            #pragma unroll
            for (int q = 0; q < 8; q++) {
                float4 h4 = hp[q];
                a0 += wr[4*q]   * h4.x;
                a1 += wr[4*q+1] * h4.y;
                a2 += wr[4*q+2] * h4.z;
                a3 += wr[4*q+3] * h4.w;
            }
            float acc = (a0 + a1) + (a2 + a3);
            acc += __shfl_xor_sync(0xffffffffu, acc, 1);
            acc += __shfl_xor_sync(0xffffffffu, acc, 2);
            acc += __shfl_xor_sync(0xffffffffu, acc, 4);
            if (sub == 0)
                publish_word(&g_xg2p[(size_t)t * 1024 + rowc], acc + bias,
                             (unsigned)(t + 1));
        }
        return;
    }

    // ---------------- recurrence layers ----------------
    int layer = blk >> 5;
    int k = blk & 31;
    int w = tid >> 5, lane = tid & 31;
    int p = lane >> 3, s = lane & 7;
    int j = k * 8 + w;           // h index 0..255
    int row = p * 256 + j;       // gate row 0..1023

    float whh[32];
    {
        const float* WhhP = whh_g + (size_t)layer * 262144 + (size_t)row * 256 + s * 32;
        #pragma unroll
        for (int c = 0; c < 32; c++) whh[c] = WhhP[c];
    }
    float bias = 0.f;
    if (layer == 0 && s == 0) bias = 0.f;   // layer-0 bias folded into g_xg

    unsigned long long* outp = (layer == 0) ? g_h1p : g_h2p;
    const unsigned long long* inp = (layer == 0) ? g_h1p : g_h2p;
    __shared__ __align__(16) float hA[2][288];   // own-layer h(t-1)
    float cst = 0.f;

    #pragma unroll 1
    for (int t = 0; t < T_STEPS; t++) {
        int buf = t & 1;
        float xg = 0.f;
        unsigned long long wx = 0ull;
        const unsigned long long* xp2 = 0;

        if (s == 0) {
            if (layer == 0) {
                xg = __ldg(&g_xg[(size_t)t * 1024 + row]);
            } else {
                // speculative xg2 load, issued BEFORE the recurrence spin
                xp2 = &g_xg2p[(size_t)t * 1024 + row];
                wx = load_word(xp2);
            }
        }

        // ---- recurrence spin: own-layer h(t-1) ----
        int pos = (tid >> 5) * 36 + (tid & 31);
        if (t > 0)
            hA[buf][pos] = poll_word(&inp[(size_t)(t - 1) * 256 + tid], (unsigned)t);
        __syncthreads();

        // ---- verify speculative xg2 (hits first try in steady state) ----
        if (layer == 1 && s == 0) {
            while ((unsigned)(wx >> 32) != (unsigned)(t + 1)) wx = load_word(xp2);
            xg = __uint_as_float((unsigned)(wx & 0xffffffffull));
        }

        // ---- gate dot products: 4 independent accumulator chains ----
        float a0 = 0.f, a1 = 0.f, a2 = 0.f, a3 = 0.f;
        if (t > 0) {
            const float4* hp = (const float4*)&hA[buf][s * 36];
            #pragma unroll
            for (int q = 0; q < 8; q++) {
                float4 h4 = hp[q];
                a0 += whh[4*q]   * h4.x;
                a1 += whh[4*q+1] * h4.y;
                a2 += whh[4*q+2] * h4.z;
                a3 += whh[4*q+3] * h4.w;
            }
        }
        float acc = (a0 + a1) + (a2 + a3);
        acc += __shfl_xor_sync(0xffffffffu, acc, 4);
        acc += __shfl_xor_sync(0xffffffffu, acc, 2);
        acc += __shfl_xor_sync(0xffffffffu, acc, 1);

        float gact = 0.f;
        if (s == 0) {
            float gv = acc + bias + xg;
            gact = (p == 2) ? tanhf(gv) : __fdividef(1.f, 1.f + __expf(-gv));
        }
        float gi = __shfl_sync(0xffffffffu, gact, 0);
        float gf = __shfl_sync(0xffffffffu, gact, 8);
        float gg = __shfl_sync(0xffffffffu, gact, 16);
        float go = __shfl_sync(0xffffffffu, gact, 24);

        if (lane == 0) {
            cst = gf * cst + gi * gg;
            float h = go * tanhf(cst);
            publish_word(&outp[(size_t)t * 256 + j], h, (unsigned)(t + 1));
        }
    }
}

// ---------------- final MLP head ----------------------------------------------
__global__ void k_head(const float* __restrict__ l1w, const float* __restrict__ l1b,
                       const float* __restrict__ l2w, const float* __restrict__ l2b,
                       float* __restrict__ out) {
    int b = blockIdx.x;
    int tid = threadIdx.x;  // 256 threads
    int w = tid >> 5, lane = tid & 31;
    __shared__ __align__(16) float hs[256];
    __shared__ float rs[128];
    __shared__ float part[8];

    hs[tid] = __uint_as_float((unsigned)(g_h2p[(size_t)b * 256 + tid] & 0xffffffffull));
    __syncthreads();

    for (int q = 0; q < 16; q++) {
        int jrow = w * 16 + q;
        const float4* wp = (const float4*)(l1w + (size_t)jrow * 256 + lane * 8);
        float4 wa = wp[0], wb = wp[1];
        const float4* hp = (const float4*)(hs + lane * 8);
        float4 haa = hp[0], hbb = hp[1];
        float acc = wa.x * haa.x + wa.y * haa.y + wa.z * haa.z + wa.w * haa.w
                  + wb.x * hbb.x + wb.y * hbb.y + wb.z * hbb.z + wb.w * hbb.w;
        #pragma unroll
        for (int sft = 16; sft > 0; sft >>= 1)
            acc += __shfl_xor_sync(0xffffffffu, acc, sft);
        if (lane == 0) rs[jrow] = fmaxf(acc + l1b[jrow], 0.f);
    }
    __syncthreads();

    float v = (tid < 128) ? rs[tid] * l2w[tid] : 0.f;
    #pragma unroll
    for (int sft = 16; sft > 0; sft >>= 1)
        v += __shfl_xor_sync(0xffffffffu, v, sft);
    if (lane == 0) part[w] = v;
    __syncthreads();
    if (tid == 0) {
        float sum = 0.f;
        #pragma unroll
        for (int i = 0; i < 8; i++) sum += part[i];
        out[b] = sum + l2b[0];
    }
}

// ---------------- launch --------------------------------------------------------
extern "C" void kernel_launch(void* const* d_in, const int* in_sizes, int n_in,
                              void* d_out, int out_size) {
    const float* x     = (const float*)d_in[0];
    const int*   ei    = (const int*)  d_in[1];
    const int*   et    = (const int*)  d_in[2];
    const int*   ui    = (const int*)  d_in[3];
    const int*   vi    = (const int*)  d_in[4];
    const float* basis = (const float*)d_in[5];
    const float* comp  = (const float*)d_in[6];
    const float* root  = (const float*)d_in[7];
    const float* cbias = (const float*)d_in[8];
    const float* w_ih  = (const float*)d_in[9];
    const float* w_hh  = (const float*)d_in[10];
    const float* b_ih  = (const float*)d_in[11];
    const float* b_hh  = (const float*)d_in[12];
    const float* l1w   = (const float*)d_in[13];
    const float* l1b   = (const float*)d_in[14];
    const float* l2w   = (const float*)d_in[15];
    const float* l2b   = (const float*)d_in[16];
    float* out = (float*)d_out;

    k_init<<<(N_NODES * R_REL + 255) / 256, 256>>>();
    k_zerotags<<<(T_STEPS * 1024 + 255) / 256, 256>>>();
    k_count<<<(E_EDGES + 255) / 256, 256>>>(ei, et);
    k_weff<<<(L_LAYERS * 32 * 192 + 255) / 256, 256>>>(basis, comp, root);

    for (int l = 0; l < L_LAYERS; l++) {
        k_transform<<<N_NODES / 32, 192>>>(x, cbias + l * 32, l);
        k_edge<<<((size_t)E_EDGES * 8) / 256, 256>>>(ei, et);
        k_tanh<<<(N_NODES * 32) / 256, 256>>>(l);
    }

    k_gather<<<(B_PAIRS * 256) / 256, 256>>>(ui, vi);
    k_xg<<<dim3(16, 64), 256>>>(w_ih, b_ih, b_hh);
    k_scan<<<96, 256>>>(w_ih, w_hh, b_ih, b_hh);
    k_head<<<B_PAIRS, 256>>>(l1w, l1b, l2w, l2b, out);
}